// round 16
// baseline (speedup 1.0000x reference)
#include <cuda_runtime.h>
#include <cuda_bf16.h>
#include <cstdint>

#define DI __device__ __forceinline__

// ============================================================================
// SpectralPoolNd: y = dht2_128( crop_center_128( dht2_256(x) ) )
// Parity-folded DHT, bf16 hi/lo 3-term mma.sync.m16n8k16.
// R16: pass1 merges the nb pair into one 512-thread CTA (warps 0-7 = E fold,
// warps 8-15 = O fold) so x is loaded/folded/split ONCE; B resident in smem.
// ============================================================================

DI uint32_t swz(int row, int kc) {
    return (uint32_t)(row * 64 + ((kc ^ ((row >> 1) & 3)) << 4));
}

// ---------------- device buffers (no allocations) ----------------
__device__ __align__(16) char g_B1f[2 * 4 * 16384];   // pass1 B [nb][4 tiles]
__device__ __align__(16) char g_L1f[2 * 8 * 16384];   // pass2 B [par][8]
__device__ __align__(16) char g_B2f[2 * 2 * 16384];   // pass3 B [nb][2]
__device__ __align__(16) char g_L2f[2 * 4 * 16384];   // pass4 B [par][4]
__device__ __align__(16) char g_Tb [512 * 16 * 16384];// pass2 A tiles [img][E8|O8]; pass4 A aliases
__device__ __align__(16) char g_Cb [512 * 4 * 16384]; // pass3 A tiles [img][E2|O2]

// ---------------- split helpers ----------------
DI uint32_t pk2(float a, float b) {
    __nv_bfloat162 t = __floats2bfloat162_rn(a, b);
    return *reinterpret_cast<uint32_t*>(&t);
}
DI void split8(const float4 v0, const float4 v1, uint4& H, uint4& L) {
    float e[8] = {v0.x, v0.y, v0.z, v0.w, v1.x, v1.y, v1.z, v1.w};
    float h[8], l[8];
    #pragma unroll
    for (int i = 0; i < 8; i++) {
        __nv_bfloat16 hb = __float2bfloat16_rn(e[i]);
        h[i] = __bfloat162float(hb);
        l[i] = e[i] - h[i];
    }
    H.x = pk2(h[0], h[1]); H.y = pk2(h[2], h[3]);
    H.z = pk2(h[4], h[5]); H.w = pk2(h[6], h[7]);
    L.x = pk2(l[0], l[1]); L.y = pk2(l[2], l[3]);
    L.z = pk2(l[4], l[5]); L.w = pk2(l[6], l[7]);
}
DI float4 f4add(float4 a, float4 b) {
    return make_float4(a.x + b.x, a.y + b.y, a.z + b.z, a.w + b.w);
}
DI float4 f4sub(float4 a, float4 b) {
    return make_float4(a.x - b.x, a.y - b.y, a.z - b.z, a.w - b.w);
}

// ---------------- constant generator (exact integer phases) ----------------
__global__ void gen_consts() {
    int e = blockIdx.x * 256 + threadIdx.x;      // 0..98303
    float v; char* base; int row; int col;
    if (e < 32768) {                             // B1f
        int nb = e >> 14, r = e & 16383;
        int n = r >> 7, w = r & 127;
        int j = 2 * (n & 63) + nb, f = 64 + j;
        float s = (n < 64) ? 1.f : -1.f;
        int ph = (f * w) & 255;
        float sn, cs; sincospif((float)ph / 128.f, &sn, &cs);
        v = cs + s * sn;
        base = g_B1f + (size_t)nb * 65536; row = n; col = w;
    } else if (e < 65536) {                      // L1f
        int r = e - 32768;
        int par = r >> 14, r2 = r & 16383;
        int me = r2 >> 8, kap = r2 & 255;
        int f = 64 + 2 * me + par;
        if (kap < 128) {
            int ph = (f * kap) & 255;
            float sn, cs; sincospif((float)ph / 128.f, &sn, &cs); v = cs;
        } else {
            int ph = (f * (kap - 128)) & 255;
            float sn, cs; sincospif((float)ph / 128.f, &sn, &cs); v = sn;
        }
        base = g_L1f + (size_t)par * 131072; row = me; col = kap;
    } else if (e < 81920) {                      // B2f
        int r = e - 65536;
        int nb = r >> 13, r2 = r & 8191;
        int n = r2 >> 6, vl = r2 & 63;
        int jw = 2 * (n & 63) + nb;
        float s = (n < 64) ? 1.f : -1.f;
        int ph = (jw * vl) & 127;
        float sn, cs; sincospif((float)ph / 64.f, &sn, &cs);
        v = cs + s * sn;
        base = g_B2f + (size_t)nb * 32768; row = n; col = vl;
    } else {                                     // L2f
        int r = e - 81920;
        int par = r >> 13, r2 = r & 8191;
        int me = r2 >> 7, kap = r2 & 127;
        int f = 2 * me + par;
        if (kap < 64) {
            int ph = (f * kap) & 127;
            float sn, cs; sincospif((float)ph / 64.f, &sn, &cs); v = cs;
        } else {
            int ph = (f * (kap - 64)) & 127;
            float sn, cs; sincospif((float)ph / 64.f, &sn, &cs); v = sn;
        }
        base = g_L2f + (size_t)par * 65536; row = me; col = kap;
    }
    __nv_bfloat16 hb = __float2bfloat16_rn(v);
    float hf = __bfloat162float(hb);
    __nv_bfloat16 lb = __float2bfloat16_rn(v - hf);
    char* p = base + (size_t)(col >> 5) * 16384 + swz(row, (col >> 3) & 3) + (col & 7) * 2;
    *(__nv_bfloat16*)p = hb;
    *(__nv_bfloat16*)(p + 8192) = lb;
}

// ---------------- PTX ----------------
DI uint32_t smem_u32(const void* p) {
    uint32_t a;
    asm("{ .reg .u64 t; cvta.to.shared.u64 t, %1; cvt.u32.u64 %0, t; }"
        : "=r"(a) : "l"(p));
    return a;
}
#define CP_A16(dst, src)                                                       \
    asm volatile("cp.async.cg.shared.global [%0], [%1], 16;"                   \
                 :: "r"(dst), "l"(src))
#define CP_COMMIT() asm volatile("cp.async.commit_group;" ::: "memory")
#define CP_WAIT1()  asm volatile("cp.async.wait_group 1;" ::: "memory")
#define CP_WAIT0()  asm volatile("cp.async.wait_group 0;" ::: "memory")

DI void mma16(float* d, const uint32_t* a, uint32_t b0, uint32_t b1) {
    asm volatile(
        "mma.sync.aligned.m16n8k16.row.col.f32.bf16.bf16.f32 "
        "{%0,%1,%2,%3}, {%4,%5,%6,%7}, {%8,%9}, {%0,%1,%2,%3};\n"
        : "+f"(d[0]), "+f"(d[1]), "+f"(d[2]), "+f"(d[3])
        : "r"(a[0]), "r"(a[1]), "r"(a[2]), "r"(a[3]), "r"(b0), "r"(b1));
}
#define LDSM4(R, A)                                                            \
    asm volatile("ldmatrix.sync.aligned.m8n8.x4.shared.b16 {%0,%1,%2,%3}, [%4];" \
                 : "=r"((R)[0]), "=r"((R)[1]), "=r"((R)[2]), "=r"((R)[3])      \
                 : "r"(A))

constexpr int STAGE = 32768;
constexpr int SMEM_P = 3 * STAGE;        // 96KB pipeline kernels (pass2-4)
constexpr int SMEM_P1 = 196608;          // pass1: B 128KB + 2 A-stages 64KB

// ---- one K=32 tile of GEMM: A at abase ([hi8K][lo8K]), B at bbase ----
template <int NACC, int WNW>
DI void gemm_tile(uint32_t abase, uint32_t bbase, int lane, int wm, int wn,
                  float (&acc)[2][8][4]) {
    #pragma unroll
    for (int kk = 0; kk < 32; kk += 16) {
        const int c0 = kk >> 3;
        uint32_t aH[2][4], aL[2][4];
        #pragma unroll
        for (int mt = 0; mt < 2; mt++) {
            const int row = wm * 32 + mt * 16 + (lane & 15);
            const int ch  = c0 + (lane >> 4);
            const uint32_t off = swz(row, ch);
            LDSM4(aH[mt], abase + off);
            LDSM4(aL[mt], abase + 8192 + off);
        }
        #pragma unroll
        for (int nt = 0; nt < NACC / 2; nt++) {
            const int nrow = wn * WNW + nt * 16 + (lane & 7) + ((lane >> 4) << 3);
            const int ch   = c0 + ((lane >> 3) & 1);
            const uint32_t off = swz(nrow, ch);
            uint32_t bh[4], bl[4];
            LDSM4(bh, bbase + off);
            LDSM4(bl, bbase + 8192 + off);
            #pragma unroll
            for (int mt = 0; mt < 2; mt++) {
                mma16(acc[mt][nt * 2],     aH[mt], bh[0], bh[1]);
                mma16(acc[mt][nt * 2],     aH[mt], bl[0], bl[1]);
                mma16(acc[mt][nt * 2],     aL[mt], bh[0], bh[1]);
                mma16(acc[mt][nt * 2 + 1], aH[mt], bh[2], bh[3]);
                mma16(acc[mt][nt * 2 + 1], aH[mt], bl[2], bl[3]);
                mma16(acc[mt][nt * 2 + 1], aL[mt], bh[2], bh[3]);
            }
        }
    }
}

// ============================================================================
// pass1 (merged nb): 512 threads; warps 0-7 -> E (nb0), warps 8-15 -> O (nb1).
// x loaded/folded/split once; both B operands smem-resident.
// smem: [B nb0 64K][B nb1 64K][Astage0: E16K|O16K][Astage1: E16K|O16K]
// Ds epilogue staging reuses the (dead) B region.
// ============================================================================
__global__ __launch_bounds__(512, 1) void pass1_fused(
    const float* __restrict__ x, const char* __restrict__ Bsrc,
    char* __restrict__ Ob)
{
    extern __shared__ char smem[];
    const uint32_t sbu = smem_u32(smem);
    const int tid = threadIdx.x, lane = tid & 31, warp = tid >> 5;
    const int g  = warp >> 3;            // fold group: 0=E, 1=O
    const int w8 = warp & 7;
    const int wm = w8 & 3, wn = w8 >> 2;
    const int mby = blockIdx.x;
    const int img = mby >> 1, half = mby & 1;
    char* Eb = Ob + (size_t)img * 262144;

    const uint32_t ASTG = 131072;        // A stages base

    float4 RA[4];                        // one chunk: a0,a1,b0,b1
    const int rr = tid >> 2, rkc = tid & 3;
    const int hh = 64 * half + ((rr < 64) ? rr : 64 + rr);
    const float* xrow = x + (size_t)img * 65536 + (size_t)hh * 256 + rkc * 8;

    auto ldgA = [&](int t) {
        const float* p = xrow + t * 32;
        RA[0] = *(const float4*)p;
        RA[1] = *(const float4*)(p + 4);
        RA[2] = *(const float4*)(p + 128);
        RA[3] = *(const float4*)(p + 132);
    };
    auto stsA = [&](int s) {
        char* base = smem + ASTG + s * 32768;
        uint32_t sw = swz(rr, rkc);
        uint4 H, L;
        split8(f4add(RA[0], RA[2]), f4add(RA[1], RA[3]), H, L);   // E
        *(uint4*)(base + sw) = H;
        *(uint4*)(base + 8192 + sw) = L;
        split8(f4sub(RA[0], RA[2]), f4sub(RA[1], RA[3]), H, L);   // O
        *(uint4*)(base + 16384 + sw) = H;
        *(uint4*)(base + 24576 + sw) = L;
    };

    // prologue: resident B (128KB), first A tile
    {
        const uint32_t o = (uint32_t)tid * 16;
        #pragma unroll
        for (int i = 0; i < 16; i++)
            CP_A16(sbu + o + i * 8192, Bsrc + o + i * 8192);
        CP_COMMIT();
    }
    ldgA(0);
    CP_WAIT0();
    stsA(0);
    __syncthreads();
    ldgA(1);

    float acc[2][8][4];
    #pragma unroll
    for (int mt = 0; mt < 2; mt++)
        #pragma unroll
        for (int q = 0; q < 8; q++)
            #pragma unroll
            for (int e = 0; e < 4; e++) acc[mt][q][e] = 0.0f;

    #pragma unroll 1
    for (int t = 0; t < 4; t++) {
        if (t + 1 < 4) {
            stsA((t + 1) & 1);
            if (t + 2 < 4) ldgA(t + 2);
        }
        gemm_tile<8, 64>(sbu + ASTG + (t & 1) * 32768 + g * 16384,
                         sbu + g * 65536 + t * 16384, lane, wm, wn, acc);
        __syncthreads();
    }

    // epilogue: per group, stage transposed Ds then fold-h emit (all threads)
    float* Ds = (float*)smem;            // reuses dead B region (67.6KB)
    #pragma unroll 1
    for (int ge = 0; ge < 2; ge++) {
        if (g == ge) {
            #pragma unroll
            for (int mt = 0; mt < 2; mt++)
                #pragma unroll
                for (int q = 0; q < 8; q++) {
                    const int n = wn * 64 + q * 8 + 2 * (lane & 3);
                    const int i = wm * 32 + mt * 16 + (lane >> 2);
                    Ds[n * 132 + i]           = acc[mt][q][0];
                    Ds[(n + 1) * 132 + i]     = acc[mt][q][1];
                    Ds[n * 132 + i + 8]       = acc[mt][q][2];
                    Ds[(n + 1) * 132 + i + 8] = acc[mt][q][3];
                }
        }
        __syncthreads();
        #pragma unroll 1
        for (int it = 0; it < 2; it++) {
            int c = it * 512 + tid;              // 1024 units
            int n = c >> 3, rf8 = (c & 7) * 8;
            const float* pr = Ds + n * 132 + rf8;
            float4 a0 = *(const float4*)pr,        a1 = *(const float4*)(pr + 4);
            float4 b0 = *(const float4*)(pr + 64), b1 = *(const float4*)(pr + 68);
            int v = 2 * (n & 63) + ge, var = n >> 6;
            int hl = 64 * half + rf8;
            int tile = var * 4 + (hl >> 5);
            uint32_t sw = swz(v, (hl >> 3) & 3);
            uint4 H, L;
            char* gE = Eb + (size_t)tile * 16384 + sw;
            split8(f4add(a0, b0), f4add(a1, b1), H, L);
            *(uint4*)gE = H; *(uint4*)(gE + 8192) = L;
            char* gO = Eb + (size_t)(8 + tile) * 16384 + sw;
            split8(f4sub(a0, b0), f4sub(a1, b1), H, L);
            *(uint4*)gO = H; *(uint4*)(gO + 8192) = L;
        }
        __syncthreads();
    }
}

// ============================================================================
// pass2: c tiles = fold_v( T * L1f^T ), per (par, img)
// ============================================================================
__global__ __launch_bounds__(256, 2) void pass2_k(
    const char* __restrict__ Asrc, const char* __restrict__ Bsrc,
    char* __restrict__ Ob)
{
    extern __shared__ char smem[];
    const uint32_t sbu = smem_u32(smem);
    const int tid = threadIdx.x, lane = tid & 31, warp = tid >> 5;
    const int wm = warp & 3, wn = warp >> 2;
    const int par = blockIdx.x, img = blockIdx.z;
    constexpr int NT = 8;

    const char* Ab = Asrc + (size_t)img * 262144 + (size_t)par * 131072;
    const char* Bb = Bsrc + (size_t)par * 131072;
    char* Eb = Ob + (size_t)img * 65536;

    auto fill = [&](uint32_t sdst, const char* sA, const char* sB) {
        const uint32_t o = (uint32_t)tid * 16;
        #pragma unroll
        for (int i = 0; i < 4; i++)
            CP_A16(sdst + o + i * 4096, sA + o + i * 4096);
        CP_A16(sdst + 16384 + o,        sB + o);
        CP_A16(sdst + 16384 + o + 8192, sB + o + 8192);
    };

    float acc[2][8][4];
    #pragma unroll
    for (int mt = 0; mt < 2; mt++)
        #pragma unroll
        for (int q = 0; q < 4; q++)
            #pragma unroll
            for (int e = 0; e < 4; e++) acc[mt][q][e] = 0.0f;

    fill(sbu,         Ab,         Bb);         CP_COMMIT();
    fill(sbu + STAGE, Ab + 16384, Bb + 16384); CP_COMMIT();
    #pragma unroll 1
    for (int t = 0; t < NT; t++) {
        if (t + 1 < NT) { CP_WAIT1(); } else { CP_WAIT0(); }
        __syncthreads();
        if (t + 2 < NT) {
            const int s = (t + 2) % 3;
            fill(sbu + s * STAGE, Ab + (size_t)(t + 2) * 16384,
                 Bb + (size_t)(t + 2) * 16384);
            CP_COMMIT();
        }
        gemm_tile<4, 32>(sbu + (t % 3) * STAGE, sbu + (t % 3) * STAGE + 16384,
                         lane, wm, wn, acc);
    }
    __syncthreads();

    float* Ds = (float*)smem;
    #pragma unroll
    for (int mt = 0; mt < 2; mt++)
        #pragma unroll
        for (int q = 0; q < 4; q++) {
            const int n = wn * 32 + q * 8 + 2 * (lane & 3);
            const int i = wm * 32 + mt * 16 + (lane >> 2);
            Ds[n * 132 + i]           = acc[mt][q][0];
            Ds[(n + 1) * 132 + i]     = acc[mt][q][1];
            Ds[n * 132 + i + 8]       = acc[mt][q][2];
            Ds[(n + 1) * 132 + i + 8] = acc[mt][q][3];
        }
    __syncthreads();
    #pragma unroll 1
    for (int it = 0; it < 2; it++) {
        int c = it * 256 + tid;
        int me = c >> 3, vl8 = (c & 7) * 8;
        const float* pr = Ds + me * 132 + vl8;
        float4 a0 = *(const float4*)pr,        a1 = *(const float4*)(pr + 4);
        float4 b0 = *(const float4*)(pr + 64), b1 = *(const float4*)(pr + 68);
        int m = 2 * me + par;
        int tile = vl8 >> 5;
        uint32_t sw = swz(m, (vl8 >> 3) & 3);
        uint4 H, L;
        char* gE = Eb + (size_t)tile * 16384 + sw;
        split8(f4add(a0, b0), f4add(a1, b1), H, L);
        *(uint4*)gE = H; *(uint4*)(gE + 8192) = L;
        char* gO = Eb + (size_t)(2 + tile) * 16384 + sw;
        split8(f4sub(a0, b0), f4sub(a1, b1), H, L);
        *(uint4*)gO = H; *(uint4*)(gO + 8192) = L;
    }
}

// ============================================================================
// pass3: u tiles = fold_m( c * B2f^T )^T, per (nb, img)
// ============================================================================
__global__ __launch_bounds__(256, 2) void pass3_k(
    const char* __restrict__ Asrc, const char* __restrict__ Bsrc,
    char* __restrict__ Ob)
{
    extern __shared__ char smem[];
    const uint32_t sbu = smem_u32(smem);
    const int tid = threadIdx.x, lane = tid & 31, warp = tid >> 5;
    const int wm = warp & 3, wn = warp >> 2;
    const int nb = blockIdx.x, img = blockIdx.z;
    constexpr int NT = 2;

    const char* Ab = Asrc + (size_t)img * 65536 + (size_t)nb * 32768;
    const char* Bb = Bsrc + (size_t)nb * 32768;
    char* Eb = Ob + (size_t)img * 131072;

    auto fill = [&](uint32_t sdst, const char* sA, const char* sB) {
        const uint32_t o = (uint32_t)tid * 16;
        #pragma unroll
        for (int i = 0; i < 4; i++)
            CP_A16(sdst + o + i * 4096, sA + o + i * 4096);
        #pragma unroll
        for (int i = 0; i < 4; i++)
            CP_A16(sdst + 16384 + o + i * 4096, sB + o + i * 4096);
    };

    float acc[2][8][4];
    #pragma unroll
    for (int mt = 0; mt < 2; mt++)
        #pragma unroll
        for (int q = 0; q < 8; q++)
            #pragma unroll
            for (int e = 0; e < 4; e++) acc[mt][q][e] = 0.0f;

    fill(sbu,         Ab,         Bb);         CP_COMMIT();
    fill(sbu + STAGE, Ab + 16384, Bb + 16384); CP_COMMIT();
    #pragma unroll 1
    for (int t = 0; t < NT; t++) {
        if (t + 1 < NT) { CP_WAIT1(); } else { CP_WAIT0(); }
        __syncthreads();
        gemm_tile<8, 64>(sbu + (t % 3) * STAGE, sbu + (t % 3) * STAGE + 16384,
                         lane, wm, wn, acc);
    }
    __syncthreads();

    float* Ds = (float*)smem;
    #pragma unroll
    for (int mt = 0; mt < 2; mt++)
        #pragma unroll
        for (int q = 0; q < 8; q++) {
            const int n = wn * 64 + q * 8 + 2 * (lane & 3);
            const int i = wm * 32 + mt * 16 + (lane >> 2);
            Ds[n * 132 + i]           = acc[mt][q][0];
            Ds[(n + 1) * 132 + i]     = acc[mt][q][1];
            Ds[n * 132 + i + 8]       = acc[mt][q][2];
            Ds[(n + 1) * 132 + i + 8] = acc[mt][q][3];
        }
    __syncthreads();
    #pragma unroll 1
    for (int it = 0; it < 4; it++) {
        int c = it * 256 + tid;
        int n = c >> 3, ml8 = (c & 7) * 8;
        const float* pr = Ds + n * 132 + ml8;
        float4 a0 = *(const float4*)pr,        a1 = *(const float4*)(pr + 4);
        float4 b0 = *(const float4*)(pr + 64), b1 = *(const float4*)(pr + 68);
        int jw = 2 * (n & 63) + nb, var = n >> 6;
        int tile = var * 2 + (ml8 >> 5);
        uint32_t sw = swz(jw, (ml8 >> 3) & 3);
        uint4 H, L;
        char* gE = Eb + (size_t)tile * 16384 + sw;
        split8(f4add(a0, b0), f4add(a1, b1), H, L);
        *(uint4*)gE = H; *(uint4*)(gE + 8192) = L;
        char* gO = Eb + (size_t)(4 + tile) * 16384 + sw;
        split8(f4sub(a0, b0), f4sub(a1, b1), H, L);
        *(uint4*)gO = H; *(uint4*)(gO + 8192) = L;
    }
}

// ============================================================================
// pass4: y = u_par * L2f^T (transposed store), per (par, img)
// ============================================================================
__global__ __launch_bounds__(256, 2) void pass4_k(
    const char* __restrict__ Asrc, const char* __restrict__ Bsrc,
    float* __restrict__ O0)
{
    extern __shared__ char smem[];
    const uint32_t sbu = smem_u32(smem);
    const int tid = threadIdx.x, lane = tid & 31, warp = tid >> 5;
    const int wm = warp & 3, wn = warp >> 2;
    const int par = blockIdx.x, img = blockIdx.z;
    constexpr int NT = 4;

    const char* Ab = Asrc + (size_t)img * 131072 + (size_t)par * 65536;
    const char* Bb = Bsrc + (size_t)par * 65536;
    float* Eo = O0 + (size_t)img * 16384;

    auto fill = [&](uint32_t sdst, const char* sA, const char* sB) {
        const uint32_t o = (uint32_t)tid * 16;
        #pragma unroll
        for (int i = 0; i < 4; i++)
            CP_A16(sdst + o + i * 4096, sA + o + i * 4096);
        CP_A16(sdst + 16384 + o,        sB + o);
        CP_A16(sdst + 16384 + o + 8192, sB + o + 8192);
    };

    float acc[2][8][4];
    #pragma unroll
    for (int mt = 0; mt < 2; mt++)
        #pragma unroll
        for (int q = 0; q < 4; q++)
            #pragma unroll
            for (int e = 0; e < 4; e++) acc[mt][q][e] = 0.0f;

    fill(sbu,         Ab,         Bb);         CP_COMMIT();
    fill(sbu + STAGE, Ab + 16384, Bb + 16384); CP_COMMIT();
    #pragma unroll 1
    for (int t = 0; t < NT; t++) {
        if (t + 1 < NT) { CP_WAIT1(); } else { CP_WAIT0(); }
        __syncthreads();
        if (t + 2 < NT) {
            const int s = (t + 2) % 3;
            fill(sbu + s * STAGE, Ab + (size_t)(t + 2) * 16384,
                 Bb + (size_t)(t + 2) * 16384);
            CP_COMMIT();
        }
        gemm_tile<4, 32>(sbu + (t % 3) * STAGE, sbu + (t % 3) * STAGE + 16384,
                         lane, wm, wn, acc);
    }
    __syncthreads();

    float* Ds = (float*)smem;
    #pragma unroll
    for (int mt = 0; mt < 2; mt++)
        #pragma unroll
        for (int q = 0; q < 4; q++) {
            const int n = wn * 32 + q * 8 + 2 * (lane & 3);
            const int i = wm * 32 + mt * 16 + (lane >> 2);
            Ds[n * 132 + i]           = acc[mt][q][0];
            Ds[(n + 1) * 132 + i]     = acc[mt][q][1];
            Ds[n * 132 + i + 8]       = acc[mt][q][2];
            Ds[(n + 1) * 132 + i + 8] = acc[mt][q][3];
        }
    __syncthreads();
    #pragma unroll 1
    for (int it = 0; it < 8; it++) {
        int c = it * 256 + tid;
        int me = c >> 5, j4 = (c & 31) * 4;
        float4 v = *(const float4*)(Ds + me * 132 + j4);
        *(float4*)(Eo + (size_t)(2 * me + par) * 128 + j4) = v;
    }
}

// ---------------- launcher ----------------
extern "C" void kernel_launch(void* const* d_in, const int* in_sizes, int n_in,
                              void* d_out, int out_size)
{
    (void)in_sizes; (void)n_in; (void)out_size;
    const float* x = (const float*)d_in[0];     // (8,64,256,256)
    float* out     = (float*)d_out;             // (8,64,128,128)

    void *pB1, *pL1, *pB2, *pL2, *pT, *pC;
    cudaGetSymbolAddress(&pB1, g_B1f);
    cudaGetSymbolAddress(&pL1, g_L1f);
    cudaGetSymbolAddress(&pB2, g_B2f);
    cudaGetSymbolAddress(&pL2, g_L2f);
    cudaGetSymbolAddress(&pT,  g_Tb);
    cudaGetSymbolAddress(&pC,  g_Cb);
    char* B1 = (char*)pB1; char* L1 = (char*)pL1;
    char* B2 = (char*)pB2; char* L2 = (char*)pL2;
    char* Tb = (char*)pT;  char* Cbp = (char*)pC;
    char* Ub = Tb;   // pass4 A tiles alias Tb (Tb dead after pass2)

    cudaFuncSetAttribute(pass1_fused, cudaFuncAttributeMaxDynamicSharedMemorySize, SMEM_P1);
    cudaFuncSetAttribute(pass2_k,     cudaFuncAttributeMaxDynamicSharedMemorySize, SMEM_P);
    cudaFuncSetAttribute(pass3_k,     cudaFuncAttributeMaxDynamicSharedMemorySize, SMEM_P);
    cudaFuncSetAttribute(pass4_k,     cudaFuncAttributeMaxDynamicSharedMemorySize, SMEM_P);

    gen_consts<<<384, 256>>>();

    // pass1: T parity groups   M=131072, N=128, K=128, both nb per CTA
    pass1_fused<<<1024, 512, SMEM_P1>>>(x, B1, Tb);
    // pass2: c parity groups   M=128(v), N=64, K=256 (x2 par per img)
    pass2_k<<<dim3(2, 1, 512), 256, SMEM_P>>>(Tb, L1, Cbp);
    // pass3: u parity groups   M=128(m), N=128, K=64 (x2 nb per img)
    pass3_k<<<dim3(2, 1, 512), 256, SMEM_P>>>(Cbp, B2, Ub);
    // pass4: y parity groups   M=128(jw), N=64, K=128 (x2 par per img)
    pass4_k<<<dim3(2, 1, 512), 256, SMEM_P>>>(Ub, L2, out);
}

// round 17
// speedup vs baseline: 1.0506x; 1.0506x over previous
#include <cuda_runtime.h>
#include <cuda_bf16.h>
#include <cstdint>

#define DI __device__ __forceinline__

// ============================================================================
// SpectralPoolNd: y = dht2_128( crop_center_128( dht2_256(x) ) )
// Parity-folded DHT, bf16 hi/lo 3-term mma.sync.m16n8k16.
// R17: pass1 = R14 proven version (fused input fold, 2 CTA/SM).
//      pass2/pass4 compact B stages (24KB) -> 3 CTAs/SM.
// ============================================================================

DI uint32_t swz(int row, int kc) {
    return (uint32_t)(row * 64 + ((kc ^ ((row >> 1) & 3)) << 4));
}

// ---------------- device buffers (no allocations) ----------------
__device__ __align__(16) char g_B1f[2 * 4 * 16384];   // pass1 B [nb][4 tiles]
__device__ __align__(16) char g_L1f[2 * 8 * 16384];   // pass2 B [par][8]
__device__ __align__(16) char g_B2f[2 * 2 * 16384];   // pass3 B [nb][2]
__device__ __align__(16) char g_L2f[2 * 4 * 16384];   // pass4 B [par][4]
__device__ __align__(16) char g_Tb [512 * 16 * 16384];// pass2 A tiles [img][E8|O8]; pass4 A aliases
__device__ __align__(16) char g_Cb [512 * 4 * 16384]; // pass3 A tiles [img][E2|O2]

// ---------------- split helpers ----------------
DI uint32_t pk2(float a, float b) {
    __nv_bfloat162 t = __floats2bfloat162_rn(a, b);
    return *reinterpret_cast<uint32_t*>(&t);
}
DI void split8(const float4 v0, const float4 v1, uint4& H, uint4& L) {
    float e[8] = {v0.x, v0.y, v0.z, v0.w, v1.x, v1.y, v1.z, v1.w};
    float h[8], l[8];
    #pragma unroll
    for (int i = 0; i < 8; i++) {
        __nv_bfloat16 hb = __float2bfloat16_rn(e[i]);
        h[i] = __bfloat162float(hb);
        l[i] = e[i] - h[i];
    }
    H.x = pk2(h[0], h[1]); H.y = pk2(h[2], h[3]);
    H.z = pk2(h[4], h[5]); H.w = pk2(h[6], h[7]);
    L.x = pk2(l[0], l[1]); L.y = pk2(l[2], l[3]);
    L.z = pk2(l[4], l[5]); L.w = pk2(l[6], l[7]);
}
DI float4 f4add(float4 a, float4 b) {
    return make_float4(a.x + b.x, a.y + b.y, a.z + b.z, a.w + b.w);
}
DI float4 f4sub(float4 a, float4 b) {
    return make_float4(a.x - b.x, a.y - b.y, a.z - b.z, a.w - b.w);
}

// ---------------- constant generator (exact integer phases) ----------------
__global__ void gen_consts() {
    int e = blockIdx.x * 256 + threadIdx.x;      // 0..98303
    float v; char* base; int row; int col;
    if (e < 32768) {                             // B1f
        int nb = e >> 14, r = e & 16383;
        int n = r >> 7, w = r & 127;
        int j = 2 * (n & 63) + nb, f = 64 + j;
        float s = (n < 64) ? 1.f : -1.f;
        int ph = (f * w) & 255;
        float sn, cs; sincospif((float)ph / 128.f, &sn, &cs);
        v = cs + s * sn;
        base = g_B1f + (size_t)nb * 65536; row = n; col = w;
    } else if (e < 65536) {                      // L1f
        int r = e - 32768;
        int par = r >> 14, r2 = r & 16383;
        int me = r2 >> 8, kap = r2 & 255;
        int f = 64 + 2 * me + par;
        if (kap < 128) {
            int ph = (f * kap) & 255;
            float sn, cs; sincospif((float)ph / 128.f, &sn, &cs); v = cs;
        } else {
            int ph = (f * (kap - 128)) & 255;
            float sn, cs; sincospif((float)ph / 128.f, &sn, &cs); v = sn;
        }
        base = g_L1f + (size_t)par * 131072; row = me; col = kap;
    } else if (e < 81920) {                      // B2f
        int r = e - 65536;
        int nb = r >> 13, r2 = r & 8191;
        int n = r2 >> 6, vl = r2 & 63;
        int jw = 2 * (n & 63) + nb;
        float s = (n < 64) ? 1.f : -1.f;
        int ph = (jw * vl) & 127;
        float sn, cs; sincospif((float)ph / 64.f, &sn, &cs);
        v = cs + s * sn;
        base = g_B2f + (size_t)nb * 32768; row = n; col = vl;
    } else {                                     // L2f
        int r = e - 81920;
        int par = r >> 13, r2 = r & 8191;
        int me = r2 >> 7, kap = r2 & 127;
        int f = 2 * me + par;
        if (kap < 64) {
            int ph = (f * kap) & 127;
            float sn, cs; sincospif((float)ph / 64.f, &sn, &cs); v = cs;
        } else {
            int ph = (f * (kap - 64)) & 127;
            float sn, cs; sincospif((float)ph / 64.f, &sn, &cs); v = sn;
        }
        base = g_L2f + (size_t)par * 65536; row = me; col = kap;
    }
    __nv_bfloat16 hb = __float2bfloat16_rn(v);
    float hf = __bfloat162float(hb);
    __nv_bfloat16 lb = __float2bfloat16_rn(v - hf);
    char* p = base + (size_t)(col >> 5) * 16384 + swz(row, (col >> 3) & 3) + (col & 7) * 2;
    *(__nv_bfloat16*)p = hb;
    *(__nv_bfloat16*)(p + 8192) = lb;
}

// ---------------- PTX ----------------
DI uint32_t smem_u32(const void* p) {
    uint32_t a;
    asm("{ .reg .u64 t; cvta.to.shared.u64 t, %1; cvt.u32.u64 %0, t; }"
        : "=r"(a) : "l"(p));
    return a;
}
#define CP_A16(dst, src)                                                       \
    asm volatile("cp.async.cg.shared.global [%0], [%1], 16;"                   \
                 :: "r"(dst), "l"(src))
#define CP_COMMIT() asm volatile("cp.async.commit_group;" ::: "memory")
#define CP_WAIT1()  asm volatile("cp.async.wait_group 1;" ::: "memory")
#define CP_WAIT0()  asm volatile("cp.async.wait_group 0;" ::: "memory")

DI void mma16(float* d, const uint32_t* a, uint32_t b0, uint32_t b1) {
    asm volatile(
        "mma.sync.aligned.m16n8k16.row.col.f32.bf16.bf16.f32 "
        "{%0,%1,%2,%3}, {%4,%5,%6,%7}, {%8,%9}, {%0,%1,%2,%3};\n"
        : "+f"(d[0]), "+f"(d[1]), "+f"(d[2]), "+f"(d[3])
        : "r"(a[0]), "r"(a[1]), "r"(a[2]), "r"(a[3]), "r"(b0), "r"(b1));
}
#define LDSM4(R, A)                                                            \
    asm volatile("ldmatrix.sync.aligned.m8n8.x4.shared.b16 {%0,%1,%2,%3}, [%4];" \
                 : "=r"((R)[0]), "=r"((R)[1]), "=r"((R)[2]), "=r"((R)[3])      \
                 : "r"(A))

constexpr int STAGE  = 32768;            // pass1/pass3 stage (full B)
constexpr int STAGE2 = 24576;            // pass2/pass4 stage (compact B: lo at +4096)
constexpr int SMEM_P  = 3 * STAGE;       // 96KB
constexpr int SMEM_P2 = 3 * STAGE2;      // 72KB; Ds (67.6KB) still fits

// ---- one K=32 tile of GEMM: A at abase ([hi8K][lo8K]), B at bbase (lo at +BLO)
template <int NACC, int WNW, int BLO>
DI void gemm_tile(uint32_t abase, uint32_t bbase, int lane, int wm, int wn,
                  float (&acc)[2][8][4]) {
    #pragma unroll
    for (int kk = 0; kk < 32; kk += 16) {
        const int c0 = kk >> 3;
        uint32_t aH[2][4], aL[2][4];
        #pragma unroll
        for (int mt = 0; mt < 2; mt++) {
            const int row = wm * 32 + mt * 16 + (lane & 15);
            const int ch  = c0 + (lane >> 4);
            const uint32_t off = swz(row, ch);
            LDSM4(aH[mt], abase + off);
            LDSM4(aL[mt], abase + 8192 + off);
        }
        #pragma unroll
        for (int nt = 0; nt < NACC / 2; nt++) {
            const int nrow = wn * WNW + nt * 16 + (lane & 7) + ((lane >> 4) << 3);
            const int ch   = c0 + ((lane >> 3) & 1);
            const uint32_t off = swz(nrow, ch);
            uint32_t bh[4], bl[4];
            LDSM4(bh, bbase + off);
            LDSM4(bl, bbase + BLO + off);
            #pragma unroll
            for (int mt = 0; mt < 2; mt++) {
                mma16(acc[mt][nt * 2],     aH[mt], bh[0], bh[1]);
                mma16(acc[mt][nt * 2],     aH[mt], bl[0], bl[1]);
                mma16(acc[mt][nt * 2],     aL[mt], bh[0], bh[1]);
                mma16(acc[mt][nt * 2 + 1], aH[mt], bh[2], bh[3]);
                mma16(acc[mt][nt * 2 + 1], aH[mt], bl[2], bl[3]);
                mma16(acc[mt][nt * 2 + 1], aL[mt], bh[2], bh[3]);
            }
        }
    }
}

// ============================================================================
// pass1 (fused input fold): T tiles = (fold_w(x) * B1f^T)^T   [R14 proven]
// ============================================================================
__global__ __launch_bounds__(256, 2) void pass1_fused(
    const float* __restrict__ x, const char* __restrict__ Bsrc,
    char* __restrict__ Ob)
{
    extern __shared__ char smem[];
    const uint32_t sbu = smem_u32(smem);
    const int tid = threadIdx.x, lane = tid & 31, warp = tid >> 5;
    const int wm = warp & 3, wn = warp >> 2;
    const int nb = blockIdx.x, mby = blockIdx.y;
    const int img = mby >> 1, half = mby & 1;
    const char* Bb = Bsrc + (size_t)nb * 65536;
    char* Eb = Ob + (size_t)img * 262144;

    float4 RA[2][4];   // [chunk][a0,a1,b0,b1]
    auto ldgA = [&](int t) {
        #pragma unroll
        for (int i = 0; i < 2; i++) {
            int c = tid + i * 256;
            int r = c >> 2, kc = c & 3;
            int h = 64 * half + ((r < 64) ? r : 64 + r);
            const float* p = x + (size_t)img * 65536 + (size_t)h * 256 + t * 32 + kc * 8;
            RA[i][0] = *(const float4*)p;
            RA[i][1] = *(const float4*)(p + 4);
            RA[i][2] = *(const float4*)(p + 128);
            RA[i][3] = *(const float4*)(p + 132);
        }
    };
    auto stsA = [&](int s) {
        char* base = smem + s * STAGE;
        #pragma unroll
        for (int i = 0; i < 2; i++) {
            int c = tid + i * 256;
            int r = c >> 2, kc = c & 3;
            float4 e0, e1;
            if (nb == 0) { e0 = f4add(RA[i][0], RA[i][2]); e1 = f4add(RA[i][1], RA[i][3]); }
            else         { e0 = f4sub(RA[i][0], RA[i][2]); e1 = f4sub(RA[i][1], RA[i][3]); }
            uint4 H, L; split8(e0, e1, H, L);
            uint32_t sw = swz(r, kc);
            *(uint4*)(base + sw) = H;
            *(uint4*)(base + 8192 + sw) = L;
        }
    };
    auto cpB = [&](int s, int t) {
        const uint32_t o = (uint32_t)tid * 16;
        const char* src = Bb + (size_t)t * 16384;
        uint32_t dst = sbu + s * STAGE + 16384;
        #pragma unroll
        for (int i = 0; i < 4; i++)
            CP_A16(dst + o + i * 4096, src + o + i * 4096);
    };

    float acc[2][8][4];
    #pragma unroll
    for (int mt = 0; mt < 2; mt++)
        #pragma unroll
        for (int q = 0; q < 8; q++)
            #pragma unroll
            for (int e = 0; e < 4; e++) acc[mt][q][e] = 0.0f;

    ldgA(0);
    cpB(0, 0); CP_COMMIT();
    cpB(1, 1); CP_COMMIT();
    stsA(0);
    ldgA(1);
    #pragma unroll 1
    for (int t = 0; t < 4; t++) {
        if (t < 3) { CP_WAIT1(); } else { CP_WAIT0(); }
        __syncthreads();
        if (t + 2 < 4) { cpB((t + 2) % 3, t + 2); CP_COMMIT(); }
        if (t + 1 < 4) {
            stsA((t + 1) % 3);
            if (t + 2 < 4) ldgA(t + 2);
        }
        gemm_tile<8, 64, 8192>(sbu + (t % 3) * STAGE, sbu + (t % 3) * STAGE + 16384,
                               lane, wm, wn, acc);
    }
    __syncthreads();

    // epilogue: transposed staging, fold h, emit E/O tiles to Tb
    float* Ds = (float*)smem;
    #pragma unroll
    for (int mt = 0; mt < 2; mt++)
        #pragma unroll
        for (int q = 0; q < 8; q++) {
            const int n = wn * 64 + q * 8 + 2 * (lane & 3);
            const int i = wm * 32 + mt * 16 + (lane >> 2);
            Ds[n * 132 + i]           = acc[mt][q][0];
            Ds[(n + 1) * 132 + i]     = acc[mt][q][1];
            Ds[n * 132 + i + 8]       = acc[mt][q][2];
            Ds[(n + 1) * 132 + i + 8] = acc[mt][q][3];
        }
    __syncthreads();
    #pragma unroll 1
    for (int it = 0; it < 4; it++) {
        int c = it * 256 + tid;
        int n = c >> 3, rf8 = (c & 7) * 8;
        const float* pr = Ds + n * 132 + rf8;
        float4 a0 = *(const float4*)pr,        a1 = *(const float4*)(pr + 4);
        float4 b0 = *(const float4*)(pr + 64), b1 = *(const float4*)(pr + 68);
        int v = 2 * (n & 63) + nb, var = n >> 6;
        int hl = 64 * half + rf8;
        int tile = var * 4 + (hl >> 5);
        uint32_t sw = swz(v, (hl >> 3) & 3);
        uint4 H, L;
        char* gE = Eb + (size_t)tile * 16384 + sw;
        split8(f4add(a0, b0), f4add(a1, b1), H, L);
        *(uint4*)gE = H; *(uint4*)(gE + 8192) = L;
        char* gO = Eb + (size_t)(8 + tile) * 16384 + sw;
        split8(f4sub(a0, b0), f4sub(a1, b1), H, L);
        *(uint4*)gO = H; *(uint4*)(gO + 8192) = L;
    }
}

// ============================================================================
// pass2: c tiles = fold_v( T * L1f^T ), per (par, img)   [compact 24KB stages]
// ============================================================================
__global__ __launch_bounds__(256, 3) void pass2_k(
    const char* __restrict__ Asrc, const char* __restrict__ Bsrc,
    char* __restrict__ Ob)
{
    extern __shared__ char smem[];
    const uint32_t sbu = smem_u32(smem);
    const int tid = threadIdx.x, lane = tid & 31, warp = tid >> 5;
    const int wm = warp & 3, wn = warp >> 2;
    const int par = blockIdx.x, img = blockIdx.z;
    constexpr int NT = 8;

    const char* Ab = Asrc + (size_t)img * 262144 + (size_t)par * 131072;
    const char* Bb = Bsrc + (size_t)par * 131072;
    char* Eb = Ob + (size_t)img * 65536;

    auto fill = [&](uint32_t sdst, const char* sA, const char* sB) {
        const uint32_t o = (uint32_t)tid * 16;
        #pragma unroll
        for (int i = 0; i < 4; i++)
            CP_A16(sdst + o + i * 4096, sA + o + i * 4096);
        CP_A16(sdst + 16384 + o,        sB + o);         // B hi rows 0-63
        CP_A16(sdst + 16384 + 4096 + o, sB + o + 8192);  // B lo rows 0-63
    };

    float acc[2][8][4];
    #pragma unroll
    for (int mt = 0; mt < 2; mt++)
        #pragma unroll
        for (int q = 0; q < 4; q++)
            #pragma unroll
            for (int e = 0; e < 4; e++) acc[mt][q][e] = 0.0f;

    fill(sbu,          Ab,         Bb);         CP_COMMIT();
    fill(sbu + STAGE2, Ab + 16384, Bb + 16384); CP_COMMIT();
    #pragma unroll 1
    for (int t = 0; t < NT; t++) {
        if (t + 1 < NT) { CP_WAIT1(); } else { CP_WAIT0(); }
        __syncthreads();
        if (t + 2 < NT) {
            const int s = (t + 2) % 3;
            fill(sbu + s * STAGE2, Ab + (size_t)(t + 2) * 16384,
                 Bb + (size_t)(t + 2) * 16384);
            CP_COMMIT();
        }
        gemm_tile<4, 32, 4096>(sbu + (t % 3) * STAGE2,
                               sbu + (t % 3) * STAGE2 + 16384, lane, wm, wn, acc);
    }
    __syncthreads();

    float* Ds = (float*)smem;
    #pragma unroll
    for (int mt = 0; mt < 2; mt++)
        #pragma unroll
        for (int q = 0; q < 4; q++) {
            const int n = wn * 32 + q * 8 + 2 * (lane & 3);
            const int i = wm * 32 + mt * 16 + (lane >> 2);
            Ds[n * 132 + i]           = acc[mt][q][0];
            Ds[(n + 1) * 132 + i]     = acc[mt][q][1];
            Ds[n * 132 + i + 8]       = acc[mt][q][2];
            Ds[(n + 1) * 132 + i + 8] = acc[mt][q][3];
        }
    __syncthreads();
    #pragma unroll 1
    for (int it = 0; it < 2; it++) {
        int c = it * 256 + tid;
        int me = c >> 3, vl8 = (c & 7) * 8;
        const float* pr = Ds + me * 132 + vl8;
        float4 a0 = *(const float4*)pr,        a1 = *(const float4*)(pr + 4);
        float4 b0 = *(const float4*)(pr + 64), b1 = *(const float4*)(pr + 68);
        int m = 2 * me + par;
        int tile = vl8 >> 5;
        uint32_t sw = swz(m, (vl8 >> 3) & 3);
        uint4 H, L;
        char* gE = Eb + (size_t)tile * 16384 + sw;
        split8(f4add(a0, b0), f4add(a1, b1), H, L);
        *(uint4*)gE = H; *(uint4*)(gE + 8192) = L;
        char* gO = Eb + (size_t)(2 + tile) * 16384 + sw;
        split8(f4sub(a0, b0), f4sub(a1, b1), H, L);
        *(uint4*)gO = H; *(uint4*)(gO + 8192) = L;
    }
}

// ============================================================================
// pass3: u tiles = fold_m( c * B2f^T )^T, per (nb, img)
// ============================================================================
__global__ __launch_bounds__(256, 2) void pass3_k(
    const char* __restrict__ Asrc, const char* __restrict__ Bsrc,
    char* __restrict__ Ob)
{
    extern __shared__ char smem[];
    const uint32_t sbu = smem_u32(smem);
    const int tid = threadIdx.x, lane = tid & 31, warp = tid >> 5;
    const int wm = warp & 3, wn = warp >> 2;
    const int nb = blockIdx.x, img = blockIdx.z;
    constexpr int NT = 2;

    const char* Ab = Asrc + (size_t)img * 65536 + (size_t)nb * 32768;
    const char* Bb = Bsrc + (size_t)nb * 32768;
    char* Eb = Ob + (size_t)img * 131072;

    auto fill = [&](uint32_t sdst, const char* sA, const char* sB) {
        const uint32_t o = (uint32_t)tid * 16;
        #pragma unroll
        for (int i = 0; i < 4; i++)
            CP_A16(sdst + o + i * 4096, sA + o + i * 4096);
        #pragma unroll
        for (int i = 0; i < 4; i++)
            CP_A16(sdst + 16384 + o + i * 4096, sB + o + i * 4096);
    };

    float acc[2][8][4];
    #pragma unroll
    for (int mt = 0; mt < 2; mt++)
        #pragma unroll
        for (int q = 0; q < 8; q++)
            #pragma unroll
            for (int e = 0; e < 4; e++) acc[mt][q][e] = 0.0f;

    fill(sbu,         Ab,         Bb);         CP_COMMIT();
    fill(sbu + STAGE, Ab + 16384, Bb + 16384); CP_COMMIT();
    #pragma unroll 1
    for (int t = 0; t < NT; t++) {
        if (t + 1 < NT) { CP_WAIT1(); } else { CP_WAIT0(); }
        __syncthreads();
        gemm_tile<8, 64, 8192>(sbu + (t % 3) * STAGE, sbu + (t % 3) * STAGE + 16384,
                               lane, wm, wn, acc);
    }
    __syncthreads();

    float* Ds = (float*)smem;
    #pragma unroll
    for (int mt = 0; mt < 2; mt++)
        #pragma unroll
        for (int q = 0; q < 8; q++) {
            const int n = wn * 64 + q * 8 + 2 * (lane & 3);
            const int i = wm * 32 + mt * 16 + (lane >> 2);
            Ds[n * 132 + i]           = acc[mt][q][0];
            Ds[(n + 1) * 132 + i]     = acc[mt][q][1];
            Ds[n * 132 + i + 8]       = acc[mt][q][2];
            Ds[(n + 1) * 132 + i + 8] = acc[mt][q][3];
        }
    __syncthreads();
    #pragma unroll 1
    for (int it = 0; it < 4; it++) {
        int c = it * 256 + tid;
        int n = c >> 3, ml8 = (c & 7) * 8;
        const float* pr = Ds + n * 132 + ml8;
        float4 a0 = *(const float4*)pr,        a1 = *(const float4*)(pr + 4);
        float4 b0 = *(const float4*)(pr + 64), b1 = *(const float4*)(pr + 68);
        int jw = 2 * (n & 63) + nb, var = n >> 6;
        int tile = var * 2 + (ml8 >> 5);
        uint32_t sw = swz(jw, (ml8 >> 3) & 3);
        uint4 H, L;
        char* gE = Eb + (size_t)tile * 16384 + sw;
        split8(f4add(a0, b0), f4add(a1, b1), H, L);
        *(uint4*)gE = H; *(uint4*)(gE + 8192) = L;
        char* gO = Eb + (size_t)(4 + tile) * 16384 + sw;
        split8(f4sub(a0, b0), f4sub(a1, b1), H, L);
        *(uint4*)gO = H; *(uint4*)(gO + 8192) = L;
    }
}

// ============================================================================
// pass4: y = u_par * L2f^T (transposed store), per (par, img) [compact stages]
// ============================================================================
__global__ __launch_bounds__(256, 3) void pass4_k(
    const char* __restrict__ Asrc, const char* __restrict__ Bsrc,
    float* __restrict__ O0)
{
    extern __shared__ char smem[];
    const uint32_t sbu = smem_u32(smem);
    const int tid = threadIdx.x, lane = tid & 31, warp = tid >> 5;
    const int wm = warp & 3, wn = warp >> 2;
    const int par = blockIdx.x, img = blockIdx.z;
    constexpr int NT = 4;

    const char* Ab = Asrc + (size_t)img * 131072 + (size_t)par * 65536;
    const char* Bb = Bsrc + (size_t)par * 65536;
    float* Eo = O0 + (size_t)img * 16384;

    auto fill = [&](uint32_t sdst, const char* sA, const char* sB) {
        const uint32_t o = (uint32_t)tid * 16;
        #pragma unroll
        for (int i = 0; i < 4; i++)
            CP_A16(sdst + o + i * 4096, sA + o + i * 4096);
        CP_A16(sdst + 16384 + o,        sB + o);
        CP_A16(sdst + 16384 + 4096 + o, sB + o + 8192);
    };

    float acc[2][8][4];
    #pragma unroll
    for (int mt = 0; mt < 2; mt++)
        #pragma unroll
        for (int q = 0; q < 4; q++)
            #pragma unroll
            for (int e = 0; e < 4; e++) acc[mt][q][e] = 0.0f;

    fill(sbu,          Ab,         Bb);         CP_COMMIT();
    fill(sbu + STAGE2, Ab + 16384, Bb + 16384); CP_COMMIT();
    #pragma unroll 1
    for (int t = 0; t < NT; t++) {
        if (t + 1 < NT) { CP_WAIT1(); } else { CP_WAIT0(); }
        __syncthreads();
        if (t + 2 < NT) {
            const int s = (t + 2) % 3;
            fill(sbu + s * STAGE2, Ab + (size_t)(t + 2) * 16384,
                 Bb + (size_t)(t + 2) * 16384);
            CP_COMMIT();
        }
        gemm_tile<4, 32, 4096>(sbu + (t % 3) * STAGE2,
                               sbu + (t % 3) * STAGE2 + 16384, lane, wm, wn, acc);
    }
    __syncthreads();

    float* Ds = (float*)smem;
    #pragma unroll
    for (int mt = 0; mt < 2; mt++)
        #pragma unroll
        for (int q = 0; q < 4; q++) {
            const int n = wn * 32 + q * 8 + 2 * (lane & 3);
            const int i = wm * 32 + mt * 16 + (lane >> 2);
            Ds[n * 132 + i]           = acc[mt][q][0];
            Ds[(n + 1) * 132 + i]     = acc[mt][q][1];
            Ds[n * 132 + i + 8]       = acc[mt][q][2];
            Ds[(n + 1) * 132 + i + 8] = acc[mt][q][3];
        }
    __syncthreads();
    #pragma unroll 1
    for (int it = 0; it < 8; it++) {
        int c = it * 256 + tid;
        int me = c >> 5, j4 = (c & 31) * 4;
        float4 v = *(const float4*)(Ds + me * 132 + j4);
        *(float4*)(Eo + (size_t)(2 * me + par) * 128 + j4) = v;
    }
}

// ---------------- launcher ----------------
extern "C" void kernel_launch(void* const* d_in, const int* in_sizes, int n_in,
                              void* d_out, int out_size)
{
    (void)in_sizes; (void)n_in; (void)out_size;
    const float* x = (const float*)d_in[0];     // (8,64,256,256)
    float* out     = (float*)d_out;             // (8,64,128,128)

    void *pB1, *pL1, *pB2, *pL2, *pT, *pC;
    cudaGetSymbolAddress(&pB1, g_B1f);
    cudaGetSymbolAddress(&pL1, g_L1f);
    cudaGetSymbolAddress(&pB2, g_B2f);
    cudaGetSymbolAddress(&pL2, g_L2f);
    cudaGetSymbolAddress(&pT,  g_Tb);
    cudaGetSymbolAddress(&pC,  g_Cb);
    char* B1 = (char*)pB1; char* L1 = (char*)pL1;
    char* B2 = (char*)pB2; char* L2 = (char*)pL2;
    char* Tb = (char*)pT;  char* Cbp = (char*)pC;
    char* Ub = Tb;   // pass4 A tiles alias Tb (Tb dead after pass2)

    cudaFuncSetAttribute(pass1_fused, cudaFuncAttributeMaxDynamicSharedMemorySize, SMEM_P);
    cudaFuncSetAttribute(pass2_k,     cudaFuncAttributeMaxDynamicSharedMemorySize, SMEM_P2);
    cudaFuncSetAttribute(pass3_k,     cudaFuncAttributeMaxDynamicSharedMemorySize, SMEM_P);
    cudaFuncSetAttribute(pass4_k,     cudaFuncAttributeMaxDynamicSharedMemorySize, SMEM_P2);

    gen_consts<<<384, 256>>>();

    // pass1: T parity groups   M=131072, N=128, K=128 (x2 nb), input fold fused
    pass1_fused<<<dim3(2, 1024, 1), 256, SMEM_P>>>(x, B1, Tb);
    // pass2: c parity groups   M=128(v), N=64, K=256 (x2 par per img)
    pass2_k<<<dim3(2, 1, 512), 256, SMEM_P2>>>(Tb, L1, Cbp);
    // pass3: u parity groups   M=128(m), N=128, K=64 (x2 nb per img)
    pass3_k<<<dim3(2, 1, 512), 256, SMEM_P>>>(Cbp, B2, Ub);
    // pass4: y parity groups   M=128(jw), N=64, K=128 (x2 par per img)
    pass4_k<<<dim3(2, 1, 512), 256, SMEM_P2>>>(Ub, L2, out);
}